// round 15
// baseline (speedup 1.0000x reference)
#include <cuda_runtime.h>
#include <cuda_bf16.h>
#include <cstdint>

// Problem constants
#define Bq  16
#define Cq  128
#define HWq 1024
#define Nq  16384   // B*H*W
#define Dq  64
#define Kq  8192

#define ZQ_ELEMS 1048576          // Nq*Dq  (z_q_st output, NCHW)
#define DIFF_OFF 1048576
#define IND_OFF  1048577

#define EPSF 0.15f                // filter margin (>= 2*bf16 deviation; validated)
#define CAP  192                  // candidate list capacity per row

// ---- scratch (device globals; no allocation allowed) ----
__device__ float          g_ze [Nq * Dq];   // z_e fp32 [N][64]
__device__ __nv_bfloat16  g_zeb[Nq * Dq];   // z_e bf16 [N][64]
__device__ __nv_bfloat16  g_eb [Kq * Dq];   // embed bf16, FRAGMENT-PERMUTED [K][64]
__device__ float          g_ce [Kq];        // ||e_k||^2 fp32
__device__ int            g_ind[Nq];        // argmin indices
__device__ int            g_cnt[Nq];        // candidate counts
__device__ int            g_cand[Nq * CAP]; // candidate code indices
__device__ float          g_part[256];      // diff partials

__device__ __forceinline__ void cpa16(uint32_t s, const void* g) {
    asm volatile("cp.async.ca.shared.global [%0], [%1], 16;" :: "r"(s), "l"(g));
}
#define CPA_COMMIT() asm volatile("cp.async.commit_group;")
#define CPA_WAIT1()  asm volatile("cp.async.wait_group 1;" ::: "memory")

__device__ __forceinline__ void mma16816(float& c0, float& c1, float& c2, float& c3,
                                         unsigned a0, unsigned a1, unsigned a2,
                                         unsigned a3, unsigned b0, unsigned b1) {
    asm("mma.sync.aligned.m16n8k16.row.col.f32.bf16.bf16.f32 "
        "{%0,%1,%2,%3}, {%4,%5,%6,%7}, {%8,%9}, {%0,%1,%2,%3};"
        : "+f"(c0), "+f"(c1), "+f"(c2), "+f"(c3)
        : "r"(a0), "r"(a1), "r"(a2), "r"(a3), "r"(b0), "r"(b1));
}

// order-preserving float->uint (for packed 64-bit min keys)
__device__ __forceinline__ unsigned ordf(float f) {
    unsigned u = __float_as_uint(f);
    return (u & 0x80000000u) ? ~u : (u | 0x80000000u);
}

// ============================================================
// Kernel A: z_e = BN(conv1x1(z))  -> g_ze (fp32) and g_zeb (bf16)
// ============================================================
__global__ __launch_bounds__(256) void k_proj(
    const float* __restrict__ z,   const float* __restrict__ w,
    const float* __restrict__ pb,  const float* __restrict__ gma,
    const float* __restrict__ bta, const float* __restrict__ rmn,
    const float* __restrict__ rvr)
{
    __shared__ float zsm[Cq * 32];   // [c][nn]
    __shared__ float wsm[Dq * Cq];   // [d][c]
    int tid = threadIdx.x;
    int n0  = blockIdx.x * 32;
    int b   = n0 >> 10, hw0 = n0 & 1023;

#pragma unroll
    for (int i = 0; i < 16; i++) {
        int idx = tid + i * 256;
        int c = idx >> 5, nn = idx & 31;
        zsm[idx] = z[(b * Cq + c) * HWq + hw0 + nn];
    }
#pragma unroll
    for (int i = 0; i < 32; i++) wsm[tid + i * 256] = w[tid + i * 256];
    __syncthreads();

    int lane = tid & 31, wd = tid >> 5;
    int d0 = wd * 8;
    float acc[8];
#pragma unroll
    for (int j = 0; j < 8; j++) acc[j] = 0.f;

#pragma unroll 4
    for (int c = 0; c < Cq; c++) {
        float a = zsm[c * 32 + lane];
#pragma unroll
        for (int j = 0; j < 8; j++)
            acc[j] = fmaf(a, wsm[(d0 + j) * Cq + c], acc[j]);
    }

    float o[8];
#pragma unroll
    for (int j = 0; j < 8; j++) {
        int d = d0 + j;
        float sc = gma[d] * (1.0f / sqrtf(rvr[d] + 1e-5f));
        float sh = bta[d] - rmn[d] * sc;
        o[j] = (acc[j] + pb[d]) * sc + sh;
    }
    float* dst = g_ze + (size_t)(n0 + lane) * Dq + d0;
    ((float4*)dst)[0] = make_float4(o[0], o[1], o[2], o[3]);
    ((float4*)dst)[1] = make_float4(o[4], o[5], o[6], o[7]);

    __nv_bfloat162 p[4];
#pragma unroll
    for (int j = 0; j < 4; j++)
        p[j] = __float22bfloat162_rn(make_float2(o[2 * j], o[2 * j + 1]));
    *(uint4*)(g_zeb + (size_t)(n0 + lane) * Dq + d0) = *(uint4*)p;
}

// ============================================================
// Kernel P: embed -> g_eb (bf16, FRAGMENT-PERMUTED), ce, zero g_cnt
// Permutation: element e = ks*16+j of code k goes to
//   d' = q*16 + ks*4 + t  with (j<8: q=j>>1,t=j&1 ; j>=8: q=(j-8)>>1,t=2+(j&1))
// so each thread's (4 ks x {b0,b1}) fragment words are 32B contiguous.
// ============================================================
__global__ __launch_bounds__(256) void k_prep(const float* __restrict__ embed)
{
    int id  = blockIdx.x * 256 + threadIdx.x;   // [0, Kq*16)
    int k   = id >> 4, seg = id & 15;
    float4 v = ((const float4*)embed)[id];
    __nv_bfloat162 b0 = __float22bfloat162_rn(make_float2(v.x, v.y));
    __nv_bfloat162 b1 = __float22bfloat162_rn(make_float2(v.z, v.w));

    int e0 = seg * 4;
    int ks = e0 >> 4;
    int j0 = e0 & 15;
    int dA = (j0 < 8) ? ((j0 >> 1) * 16 + ks * 4)
                      : (((j0 - 8) >> 1) * 16 + ks * 4 + 2);
    int j2 = j0 + 2;
    int dB = (j2 < 8) ? ((j2 >> 1) * 16 + ks * 4)
                      : (((j2 - 8) >> 1) * 16 + ks * 4 + 2);
    *(unsigned*)(g_eb + (size_t)k * Dq + dA) = *(unsigned*)&b0;
    *(unsigned*)(g_eb + (size_t)k * Dq + dB) = *(unsigned*)&b1;

    float s = v.x * v.x + v.y * v.y + v.z * v.z + v.w * v.w;
    s += __shfl_xor_sync(0xffffffffu, s, 1);
    s += __shfl_xor_sync(0xffffffffu, s, 2);
    s += __shfl_xor_sync(0xffffffffu, s, 4);
    s += __shfl_xor_sync(0xffffffffu, s, 8);
    if (seg == 0) g_ce[k] = s;
    if (id < Nq) g_cnt[id] = 0;                 // reset per replay
}

// ============================================================
// Dummy kernel: positions k_argmin as our 4th launch so ncu's
// "-s 5 -c 1" (which lands on our launch #4) captures k_argmin.
// ============================================================
__global__ void k_dummy() {}

// ============================================================
// Kernel C: single-sweep bf16 MMA filter -> per-row candidate lists
// CTA: 64 rows x all K. Chunk = 256 codes, 3-buffer cp.async ring,
// z tile staged inside ring buffer 0. Fragment-permuted embed rows:
// per nt the b-fragments for all 4 ks arrive as 2 x LDS.128 (was 8
// LDS.32). Lagged quad threshold; chunk 0 revisited at the end.
// ============================================================

// smem byte offsets (16B aligned)
#define SM_EB    0         // bf16 e chunk  3x[256][144B]  -> 110592 B
#define SM_CE    110592    // ce chunk      3x256 f        ->   3072 B
#define SM_TOTAL 113664
#define EBBUF    36864
#define NITER    33        // 32 chunks + revisit of chunk 0

__global__ __launch_bounds__(256, 2) void k_argmin()
{
    extern __shared__ char sm[];
    char*  ebB  = sm + SM_EB;
    char*  zsbB = sm;                   // z tile overlays ring buffer 0
    float* cesm = (float*)(sm + SM_CE);
    uint32_t smemu = (uint32_t)__cvta_generic_to_shared(sm);

    int tid = threadIdx.x;
    int l   = tid & 31, w = tid >> 5;
    int n0  = blockIdx.x * 64;
    int mbase = (w & 3) * 16;           // m16 tile
    int nhalf = (w >> 2) * 128;         // 128-code half of 256-code chunk
    int lg = l >> 2, lq = l & 3;        // fragment coords

    // ---- stage bf16 z tile [64][144B] into buffer 0 region, extract A ----
    // (z tile keeps the ORIGINAL [row][d] layout; only embed is permuted)
#pragma unroll
    for (int i = 0; i < 2; i++) {
        int g = tid + i * 256;
        int r = g >> 3, s = g & 7;
        *(uint4*)(zsbB + r * 144 + s * 16) =
            *(const uint4*)(g_zeb + (size_t)(n0 + r) * Dq + s * 8);
    }
    __syncthreads();

    int r0 = mbase + lg, r1 = r0 + 8;
    int row0 = n0 + r0, row1 = n0 + r1;

    unsigned af[4][4];
#pragma unroll
    for (int ks = 0; ks < 4; ks++) {
        int cb = (ks * 16 + lq * 2) * 2;       // byte col
        af[ks][0] = *(const unsigned*)(zsbB + r0 * 144 + cb);
        af[ks][1] = *(const unsigned*)(zsbB + r1 * 144 + cb);
        af[ks][2] = *(const unsigned*)(zsbB + r0 * 144 + cb + 16);
        af[ks][3] = *(const unsigned*)(zsbB + r1 * 144 + cb + 16);
    }
    __syncthreads();    // everyone extracted; buffer 0 may now be overwritten

    // prefetch by ITERATION index (chunk = it mod 32, ring buffer = it mod 3)
    auto prefetch = [&](int it) {
        int c   = (it < 32) ? it : it - 32;
        int buf = it % 3;
#pragma unroll
        for (int i = 0; i < 8; i++) {
            int g = tid + i * 256;          // 0..2047 = code*8 + seg
            int code = g >> 3, seg = g & 7;
            cpa16(smemu + SM_EB + buf * EBBUF + code * 144 + seg * 16,
                  g_eb + (size_t)(c * 256 + code) * Dq + seg * 8);
        }
        if (tid < 64)
            cpa16(smemu + SM_CE + buf * 1024 + tid * 16, g_ce + c * 256 + tid * 4);
    };

    prefetch(0); CPA_COMMIT();
    prefetch(1); CPA_COMMIT();

    float run0 = 3.0e38f, run1 = 3.0e38f;   // quad-shared minima (lagged)

    for (int it = 0; it < NITER; it++) {
        CPA_WAIT1();
        __syncthreads();      // chunk data ready; all warps done with prev buf
        if (it + 2 < NITER) prefetch(it + 2);   // into buf (it+2)%3 == (it-1)%3
        CPA_COMMIT();

        int buf = it % 3;
        int c   = (it < 32) ? it : it - 32;
        bool app = (it >= 1);                  // chunk 0 appended on revisit
        const char*  eb = ebB + buf * EBBUF;
        const float* ce = cesm + buf * 256;

        float t0 = run0 + EPSF, t1 = run1 + EPSF;   // lagged thresholds
        float cm0 = 3.0e38f, cm1 = 3.0e38f;         // chunk-local minima

#pragma unroll
        for (int nt = 0; nt < 16; nt++) {
            float c0 = 0.f, c1 = 0.f, c2 = 0.f, c3 = 0.f;
            int crow = nhalf + nt * 8 + lg;
            // fragment-permuted layout: this thread's 8 b-words contiguous
            const char* ebrow = eb + crow * 144 + lq * 32;
            uint4 v0 = *(const uint4*)(ebrow);
            uint4 v1 = *(const uint4*)(ebrow + 16);
            mma16816(c0, c1, c2, c3, af[0][0], af[0][1], af[0][2], af[0][3],
                     v0.x, v0.y);
            mma16816(c0, c1, c2, c3, af[1][0], af[1][1], af[1][2], af[1][3],
                     v0.z, v0.w);
            mma16816(c0, c1, c2, c3, af[2][0], af[2][1], af[2][2], af[2][3],
                     v1.x, v1.y);
            mma16816(c0, c1, c2, c3, af[3][0], af[3][1], af[3][2], af[3][3],
                     v1.z, v1.w);

            int cloc = nhalf + nt * 8 + 2 * lq;    // this thread's code pair
            float2 cp = *(const float2*)(ce + cloc);
            float s0 = fmaf(-2.f, c0, cp.x);
            float s1 = fmaf(-2.f, c1, cp.y);
            float s2 = fmaf(-2.f, c2, cp.x);
            float s3 = fmaf(-2.f, c3, cp.y);

            cm0 = fminf(cm0, fminf(s0, s1));
            cm1 = fminf(cm1, fminf(s2, s3));

            if (app) {
                bool p0 = s0 <= t0, p1 = s1 <= t0;
                bool p2 = s2 <= t1, p3 = s3 <= t1;
                // warp-uniform guard: almost always false after warm-up
                if (__any_sync(0xffffffffu, p0 | p1 | p2 | p3)) {
                    int kb = c * 256 + cloc;
                    if (p0) { int i = atomicAdd(&g_cnt[row0], 1);
                              if (i < CAP) g_cand[(size_t)row0 * CAP + i] = kb; }
                    if (p1) { int i = atomicAdd(&g_cnt[row0], 1);
                              if (i < CAP) g_cand[(size_t)row0 * CAP + i] = kb + 1; }
                    if (p2) { int i = atomicAdd(&g_cnt[row1], 1);
                              if (i < CAP) g_cand[(size_t)row1 * CAP + i] = kb; }
                    if (p3) { int i = atomicAdd(&g_cnt[row1], 1);
                              if (i < CAP) g_cand[(size_t)row1 * CAP + i] = kb + 1; }
                }
            }
        }

        // one quad reduce per chunk (2 shfl per row-group)
        cm0 = fminf(cm0, __shfl_xor_sync(0xffffffffu, cm0, 1));
        cm0 = fminf(cm0, __shfl_xor_sync(0xffffffffu, cm0, 2));
        run0 = fminf(run0, cm0);
        cm1 = fminf(cm1, __shfl_xor_sync(0xffffffffu, cm1, 1));
        cm1 = fminf(cm1, __shfl_xor_sync(0xffffffffu, cm1, 2));
        run1 = fminf(run1, cm1);
    }
}

// ============================================================
// Kernel R: exact rescore (R3 fp32 chain) with coalesced smem staging.
// One warp per row; batches of 16 candidates staged [16][68]
// (conflict-free); lanes 0-15 run the exact chain. Lowest-index
// tie-break via packed 64-bit key.
// ============================================================
__global__ __launch_bounds__(256) void k_refine(const float* __restrict__ embed)
{
    __shared__ float sbuf[8][16][68];   // [warp][cand][d(+pad)] = 34816 B
    int w = threadIdx.x >> 5, l = threadIdx.x & 31;
    int n = blockIdx.x * 8 + w;
    const float* zr = g_ze + (size_t)n * Dq;

    // szz: identical sequential chain on every lane (warp-uniform loads)
    float szz = 0.f;
#pragma unroll
    for (int d = 0; d < Dq; d++) szz = fmaf(zr[d], zr[d], szz);

    int cnt = g_cnt[n];
    bool ovf = (cnt > CAP);
    int total = ovf ? Kq : cnt;
    unsigned long long best = ~0ull;

    for (int base = 0; base < total; base += 16) {
        int nval = min(16, total - base);
        // lane j < nval holds candidate index
        int kj = 0;
        if (l < nval) kj = ovf ? (base + l) : g_cand[(size_t)n * CAP + base + l];

        // stage nval embed rows coalesced: 16 float4 per row
#pragma unroll
        for (int i = 0; i < 8; i++) {
            int idx = l + i * 32;           // 0..255 = row*16 + seg
            int row = idx >> 4, seg = idx & 15;
            int kr = __shfl_sync(0xffffffffu, kj, row);
            if (row < nval)
                *(float4*)&sbuf[w][row][seg * 4] =
                    *(const float4*)(embed + (size_t)kr * Dq + seg * 4);
        }
        __syncwarp();

        if (l < nval) {
            const float* er = sbuf[w][l];
            float lo = 0.f, hi = 0.f;
#pragma unroll
            for (int d = 0; d < 32; d++) {  // exact even/odd chain (R3)
                lo = fmaf(zr[2 * d],     er[2 * d],     lo);
                hi = fmaf(zr[2 * d + 1], er[2 * d + 1], hi);
            }
            float m = fmaf(-2.0f, lo + hi, szz) + __ldg(&g_ce[kj]);
            unsigned long long key =
                ((unsigned long long)ordf(m) << 32) | (unsigned)kj;
            best = min(best, key);
        }
        __syncwarp();
    }

#pragma unroll
    for (int o = 16; o; o >>= 1) {
        unsigned long long ob = __shfl_xor_sync(0xffffffffu, best, o);
        best = min(best, ob);
    }
    if (l == 0) g_ind[n] = (int)(best & 0xFFFFFFFFu);
}

// ============================================================
// Kernel D: gather z_q, straight-through out (NCHW), ind, diff partials
// ============================================================
__global__ __launch_bounds__(64) void k_out(const float* __restrict__ embed,
                                            float* __restrict__ out, int out_size)
{
    __shared__ float red[64];
    int tid = threadIdx.x;
    int n   = blockIdx.x * 64 + tid;
    int b   = n >> 10, hw = n & 1023;
    int ind = g_ind[n];
    const float4* q4 = (const float4*)(embed + (size_t)ind * Dq);
    const float4* e4 = (const float4*)(g_ze + (size_t)n * Dq);
    float* ob = out + b * 65536 + hw;
    bool wrq = (out_size >= ZQ_ELEMS);
    float ss = 0.f;
#pragma unroll
    for (int i = 0; i < 16; i++) {
        float4 q = q4[i], e = e4[i];
        float dx = q.x - e.x, dy = q.y - e.y, dz = q.z - e.z, dw = q.w - e.w;
        ss += dx * dx + dy * dy + dz * dz + dw * dw;
        if (wrq) {
            ob[(4 * i + 0) * 1024] = e.x + dx;
            ob[(4 * i + 1) * 1024] = e.y + dy;
            ob[(4 * i + 2) * 1024] = e.z + dz;
            ob[(4 * i + 3) * 1024] = e.w + dw;
        }
    }
    if (out_size >= IND_OFF + Nq) out[IND_OFF + n] = (float)ind;

    red[tid] = ss;
    __syncthreads();
    for (int s = 32; s; s >>= 1) {
        if (tid < s) red[tid] += red[tid + s];
        __syncthreads();
    }
    if (tid == 0) g_part[blockIdx.x] = red[0];
}

// ============================================================
// Kernel E: deterministic final reduce -> diff scalar
// ============================================================
__global__ void k_diff(float* __restrict__ out, int out_size) {
    if (threadIdx.x == 0 && out_size >= DIFF_OFF + 1) {
        float s = 0.f;
        for (int i = 0; i < 256; i++) s += g_part[i];
        float m = s * (1.0f / 1048576.0f);           // mean over B*H*W*D
        out[DIFF_OFF] = 10.0f * (0.25f * m + m);     // KLD_SCALE*(COMMIT*m + m)
    }
}

extern "C" void kernel_launch(void* const* d_in, const int* in_sizes, int n_in,
                              void* d_out, int out_size)
{
    const float* z     = (const float*)d_in[0];   // [16,128,32,32]
    const float* pw    = (const float*)d_in[1];   // [64,128]
    const float* pb    = (const float*)d_in[2];   // [64]
    const float* gma   = (const float*)d_in[3];   // [64]
    const float* bta   = (const float*)d_in[4];   // [64]
    const float* rmn   = (const float*)d_in[5];   // [64]
    const float* rvr   = (const float*)d_in[6];   // [64]
    const float* embed = (const float*)d_in[7];   // [8192,64]
    float* out = (float*)d_out;

    cudaFuncSetAttribute(k_argmin, cudaFuncAttributeMaxDynamicSharedMemorySize,
                         SM_TOTAL);

    k_proj  <<<Nq / 32, 256>>>(z, pw, pb, gma, bta, rmn, rvr);
    k_prep  <<<Kq * 16 / 256, 256>>>(embed);
    k_dummy <<<1, 32>>>();      // positions k_argmin as our 4th launch (ncu)
    k_argmin<<<Nq / 64, 256, SM_TOTAL>>>();
    k_refine<<<Nq / 8, 256>>>(embed);
    k_out   <<<Nq / 64, 64>>>(embed, out, out_size);
    k_diff  <<<1, 32>>>(out, out_size);
}

// round 16
// speedup vs baseline: 1.4718x; 1.4718x over previous
#include <cuda_runtime.h>
#include <cuda_bf16.h>
#include <cstdint>

// Problem constants
#define Bq  16
#define Cq  128
#define HWq 1024
#define Nq  16384   // B*H*W
#define Dq  64
#define Kq  8192

#define ZQ_ELEMS 1048576          // Nq*Dq  (z_q_st output, NCHW)
#define DIFF_OFF 1048576
#define IND_OFF  1048577

#define EPSF 0.15f                // filter margin (>= 2*bf16 deviation; validated)
#define CAP  192                  // candidate list capacity per row

// ---- scratch (device globals; no allocation allowed) ----
__device__ float          g_ze [Nq * Dq];   // z_e fp32 [N][64]
__device__ __nv_bfloat16  g_zeb[Nq * Dq];   // z_e bf16 [N][64]
__device__ __nv_bfloat16  g_eb [Kq * Dq];   // embed bf16 [K][64]
__device__ float          g_ce [Kq];        // ||e_k||^2 fp32
__device__ int            g_ind[Nq];        // argmin indices
__device__ int            g_cnt[Nq];        // candidate counts
__device__ int            g_cand[Nq * CAP]; // candidate code indices
__device__ float          g_part[256];      // diff partials

__device__ __forceinline__ void cpa16(uint32_t s, const void* g) {
    asm volatile("cp.async.ca.shared.global [%0], [%1], 16;" :: "r"(s), "l"(g));
}
#define CPA_COMMIT() asm volatile("cp.async.commit_group;")
#define CPA_WAIT1()  asm volatile("cp.async.wait_group 1;" ::: "memory")

__device__ __forceinline__ void mma16816(float& c0, float& c1, float& c2, float& c3,
                                         unsigned a0, unsigned a1, unsigned a2,
                                         unsigned a3, unsigned b0, unsigned b1) {
    asm("mma.sync.aligned.m16n8k16.row.col.f32.bf16.bf16.f32 "
        "{%0,%1,%2,%3}, {%4,%5,%6,%7}, {%8,%9}, {%0,%1,%2,%3};"
        : "+f"(c0), "+f"(c1), "+f"(c2), "+f"(c3)
        : "r"(a0), "r"(a1), "r"(a2), "r"(a3), "r"(b0), "r"(b1));
}

// order-preserving float->uint (for packed 64-bit min keys)
__device__ __forceinline__ unsigned ordf(float f) {
    unsigned u = __float_as_uint(f);
    return (u & 0x80000000u) ? ~u : (u | 0x80000000u);
}

// ============================================================
// Kernel A: z_e = BN(conv1x1(z))  -> g_ze (fp32) and g_zeb (bf16)
// ============================================================
__global__ __launch_bounds__(256) void k_proj(
    const float* __restrict__ z,   const float* __restrict__ w,
    const float* __restrict__ pb,  const float* __restrict__ gma,
    const float* __restrict__ bta, const float* __restrict__ rmn,
    const float* __restrict__ rvr)
{
    __shared__ float zsm[Cq * 32];   // [c][nn]
    __shared__ float wsm[Dq * Cq];   // [d][c]
    int tid = threadIdx.x;
    int n0  = blockIdx.x * 32;
    int b   = n0 >> 10, hw0 = n0 & 1023;

#pragma unroll
    for (int i = 0; i < 16; i++) {
        int idx = tid + i * 256;
        int c = idx >> 5, nn = idx & 31;
        zsm[idx] = z[(b * Cq + c) * HWq + hw0 + nn];
    }
#pragma unroll
    for (int i = 0; i < 32; i++) wsm[tid + i * 256] = w[tid + i * 256];
    __syncthreads();

    int lane = tid & 31, wd = tid >> 5;
    int d0 = wd * 8;
    float acc[8];
#pragma unroll
    for (int j = 0; j < 8; j++) acc[j] = 0.f;

#pragma unroll 4
    for (int c = 0; c < Cq; c++) {
        float a = zsm[c * 32 + lane];
#pragma unroll
        for (int j = 0; j < 8; j++)
            acc[j] = fmaf(a, wsm[(d0 + j) * Cq + c], acc[j]);
    }

    float o[8];
#pragma unroll
    for (int j = 0; j < 8; j++) {
        int d = d0 + j;
        float sc = gma[d] * (1.0f / sqrtf(rvr[d] + 1e-5f));
        float sh = bta[d] - rmn[d] * sc;
        o[j] = (acc[j] + pb[d]) * sc + sh;
    }
    float* dst = g_ze + (size_t)(n0 + lane) * Dq + d0;
    ((float4*)dst)[0] = make_float4(o[0], o[1], o[2], o[3]);
    ((float4*)dst)[1] = make_float4(o[4], o[5], o[6], o[7]);

    __nv_bfloat162 p[4];
#pragma unroll
    for (int j = 0; j < 4; j++)
        p[j] = __float22bfloat162_rn(make_float2(o[2 * j], o[2 * j + 1]));
    *(uint4*)(g_zeb + (size_t)(n0 + lane) * Dq + d0) = *(uint4*)p;
}

// ============================================================
// Kernel P: embed -> g_eb (bf16, PLAIN layout), ce, zero g_cnt
// ============================================================
__global__ __launch_bounds__(256) void k_prep(const float* __restrict__ embed)
{
    int id  = blockIdx.x * 256 + threadIdx.x;   // [0, Kq*16)
    int k   = id >> 4, seg = id & 15;
    float4 v = ((const float4*)embed)[id];
    __nv_bfloat162 b0 = __float22bfloat162_rn(make_float2(v.x, v.y));
    __nv_bfloat162 b1 = __float22bfloat162_rn(make_float2(v.z, v.w));
    uint2 pk; pk.x = *(unsigned*)&b0; pk.y = *(unsigned*)&b1;
    *(uint2*)(g_eb + (size_t)k * Dq + seg * 4) = pk;

    float s = v.x * v.x + v.y * v.y + v.z * v.z + v.w * v.w;
    s += __shfl_xor_sync(0xffffffffu, s, 1);
    s += __shfl_xor_sync(0xffffffffu, s, 2);
    s += __shfl_xor_sync(0xffffffffu, s, 4);
    s += __shfl_xor_sync(0xffffffffu, s, 8);
    if (seg == 0) g_ce[k] = s;
    if (id < Nq) g_cnt[id] = 0;                 // reset per replay
}

// ============================================================
// Dummy kernel: positions k_argmin as our 4th launch (ncu -s 5 -c 1)
// ============================================================
__global__ void k_dummy() {}

// ============================================================
// Kernel C: single-sweep bf16 MMA filter -> per-row candidate lists
// CTA: 64 rows x all K. Chunk = 256 codes, 3-buffer cp.async ring, z
// tile staged inside ring buffer 0. ILP fix: per nt the 4 ks-MMAs are
// SPLIT into two independent accumulator quads (chain 4 -> 2), summed
// at score time — doubles tensor-pipe overlap at 2 CTAs/SM occupancy.
// Lagged quad threshold; chunk 0 revisited at the end.
// ============================================================

// smem byte offsets (16B aligned)
#define SM_EB    0         // bf16 e chunk  3x[256][144B]  -> 110592 B
#define SM_CE    110592    // ce chunk      3x256 f        ->   3072 B
#define SM_TOTAL 113664
#define EBBUF    36864
#define NITER    33        // 32 chunks + revisit of chunk 0

__global__ __launch_bounds__(256, 2) void k_argmin()
{
    extern __shared__ char sm[];
    char*  ebB  = sm + SM_EB;
    char*  zsbB = sm;                   // z tile overlays ring buffer 0
    float* cesm = (float*)(sm + SM_CE);
    uint32_t smemu = (uint32_t)__cvta_generic_to_shared(sm);

    int tid = threadIdx.x;
    int l   = tid & 31, w = tid >> 5;
    int n0  = blockIdx.x * 64;
    int mbase = (w & 3) * 16;           // m16 tile
    int nhalf = (w >> 2) * 128;         // 128-code half of 256-code chunk
    int lg = l >> 2, lq = l & 3;        // fragment coords

    // ---- stage bf16 z tile [64][144B] into buffer 0 region, extract A ----
#pragma unroll
    for (int i = 0; i < 2; i++) {
        int g = tid + i * 256;
        int r = g >> 3, s = g & 7;
        *(uint4*)(zsbB + r * 144 + s * 16) =
            *(const uint4*)(g_zeb + (size_t)(n0 + r) * Dq + s * 8);
    }
    __syncthreads();

    int r0 = mbase + lg, r1 = r0 + 8;
    int row0 = n0 + r0, row1 = n0 + r1;

    unsigned af[4][4];
#pragma unroll
    for (int ks = 0; ks < 4; ks++) {
        int cb = (ks * 16 + lq * 2) * 2;       // byte col
        af[ks][0] = *(const unsigned*)(zsbB + r0 * 144 + cb);
        af[ks][1] = *(const unsigned*)(zsbB + r1 * 144 + cb);
        af[ks][2] = *(const unsigned*)(zsbB + r0 * 144 + cb + 16);
        af[ks][3] = *(const unsigned*)(zsbB + r1 * 144 + cb + 16);
    }
    __syncthreads();    // everyone extracted; buffer 0 may now be overwritten

    // prefetch by ITERATION index (chunk = it mod 32, ring buffer = it mod 3)
    auto prefetch = [&](int it) {
        int c   = (it < 32) ? it : it - 32;
        int buf = it % 3;
#pragma unroll
        for (int i = 0; i < 8; i++) {
            int g = tid + i * 256;          // 0..2047 = code*8 + seg
            int code = g >> 3, seg = g & 7;
            cpa16(smemu + SM_EB + buf * EBBUF + code * 144 + seg * 16,
                  g_eb + (size_t)(c * 256 + code) * Dq + seg * 8);
        }
        if (tid < 64)
            cpa16(smemu + SM_CE + buf * 1024 + tid * 16, g_ce + c * 256 + tid * 4);
    };

    prefetch(0); CPA_COMMIT();
    prefetch(1); CPA_COMMIT();

    float run0 = 3.0e38f, run1 = 3.0e38f;   // quad-shared minima (lagged)

    for (int it = 0; it < NITER; it++) {
        CPA_WAIT1();
        __syncthreads();      // chunk data ready; all warps done with prev buf
        if (it + 2 < NITER) prefetch(it + 2);   // into buf (it+2)%3 == (it-1)%3
        CPA_COMMIT();

        int buf = it % 3;
        int c   = (it < 32) ? it : it - 32;
        bool app = (it >= 1);                  // chunk 0 appended on revisit
        const char*  eb = ebB + buf * EBBUF;
        const float* ce = cesm + buf * 256;

        float t0 = run0 + EPSF, t1 = run1 + EPSF;   // lagged thresholds
        float cm0 = 3.0e38f, cm1 = 3.0e38f;         // chunk-local minima

#pragma unroll
        for (int nt = 0; nt < 16; nt++) {
            // two INDEPENDENT accumulator quads (ks0/1 and ks2/3):
            // MMA dependency chain length 2 instead of 4.
            float x0 = 0.f, x1 = 0.f, x2 = 0.f, x3 = 0.f;
            float y0 = 0.f, y1 = 0.f, y2 = 0.f, y3 = 0.f;
            int crow = nhalf + nt * 8 + lg;
            {
                int cb0 = (0 * 16 + lq * 2) * 2;
                unsigned b0 = *(const unsigned*)(eb + crow * 144 + cb0);
                unsigned b1 = *(const unsigned*)(eb + crow * 144 + cb0 + 16);
                mma16816(x0, x1, x2, x3,
                         af[0][0], af[0][1], af[0][2], af[0][3], b0, b1);
            }
            {
                int cb2 = (2 * 16 + lq * 2) * 2;
                unsigned b0 = *(const unsigned*)(eb + crow * 144 + cb2);
                unsigned b1 = *(const unsigned*)(eb + crow * 144 + cb2 + 16);
                mma16816(y0, y1, y2, y3,
                         af[2][0], af[2][1], af[2][2], af[2][3], b0, b1);
            }
            {
                int cb1 = (1 * 16 + lq * 2) * 2;
                unsigned b0 = *(const unsigned*)(eb + crow * 144 + cb1);
                unsigned b1 = *(const unsigned*)(eb + crow * 144 + cb1 + 16);
                mma16816(x0, x1, x2, x3,
                         af[1][0], af[1][1], af[1][2], af[1][3], b0, b1);
            }
            {
                int cb3 = (3 * 16 + lq * 2) * 2;
                unsigned b0 = *(const unsigned*)(eb + crow * 144 + cb3);
                unsigned b1 = *(const unsigned*)(eb + crow * 144 + cb3 + 16);
                mma16816(y0, y1, y2, y3,
                         af[3][0], af[3][1], af[3][2], af[3][3], b0, b1);
            }

            int cloc = nhalf + nt * 8 + 2 * lq;    // this thread's code pair
            float2 cp = *(const float2*)(ce + cloc);
            float s0 = fmaf(-2.f, x0 + y0, cp.x);
            float s1 = fmaf(-2.f, x1 + y1, cp.y);
            float s2 = fmaf(-2.f, x2 + y2, cp.x);
            float s3 = fmaf(-2.f, x3 + y3, cp.y);

            cm0 = fminf(cm0, fminf(s0, s1));
            cm1 = fminf(cm1, fminf(s2, s3));

            if (app) {
                bool p0 = s0 <= t0, p1 = s1 <= t0;
                bool p2 = s2 <= t1, p3 = s3 <= t1;
                // warp-uniform guard: almost always false after warm-up
                if (__any_sync(0xffffffffu, p0 | p1 | p2 | p3)) {
                    int kb = c * 256 + cloc;
                    if (p0) { int i = atomicAdd(&g_cnt[row0], 1);
                              if (i < CAP) g_cand[(size_t)row0 * CAP + i] = kb; }
                    if (p1) { int i = atomicAdd(&g_cnt[row0], 1);
                              if (i < CAP) g_cand[(size_t)row0 * CAP + i] = kb + 1; }
                    if (p2) { int i = atomicAdd(&g_cnt[row1], 1);
                              if (i < CAP) g_cand[(size_t)row1 * CAP + i] = kb; }
                    if (p3) { int i = atomicAdd(&g_cnt[row1], 1);
                              if (i < CAP) g_cand[(size_t)row1 * CAP + i] = kb + 1; }
                }
            }
        }

        // one quad reduce per chunk (2 shfl per row-group)
        cm0 = fminf(cm0, __shfl_xor_sync(0xffffffffu, cm0, 1));
        cm0 = fminf(cm0, __shfl_xor_sync(0xffffffffu, cm0, 2));
        run0 = fminf(run0, cm0);
        cm1 = fminf(cm1, __shfl_xor_sync(0xffffffffu, cm1, 1));
        cm1 = fminf(cm1, __shfl_xor_sync(0xffffffffu, cm1, 2));
        run1 = fminf(run1, cm1);
    }
}

// ============================================================
// Kernel R: exact rescore (R3 fp32 chain) with coalesced smem staging.
// One warp per row; batches of 16 candidates staged [16][68]
// (conflict-free); lanes 0-15 run the exact chain. Lowest-index
// tie-break via packed 64-bit key.
// ============================================================
__global__ __launch_bounds__(256) void k_refine(const float* __restrict__ embed)
{
    __shared__ float sbuf[8][16][68];   // [warp][cand][d(+pad)] = 34816 B
    int w = threadIdx.x >> 5, l = threadIdx.x & 31;
    int n = blockIdx.x * 8 + w;
    const float* zr = g_ze + (size_t)n * Dq;

    // szz: identical sequential chain on every lane (warp-uniform loads)
    float szz = 0.f;
#pragma unroll
    for (int d = 0; d < Dq; d++) szz = fmaf(zr[d], zr[d], szz);

    int cnt = g_cnt[n];
    bool ovf = (cnt > CAP);
    int total = ovf ? Kq : cnt;
    unsigned long long best = ~0ull;

    for (int base = 0; base < total; base += 16) {
        int nval = min(16, total - base);
        // lane j < nval holds candidate index
        int kj = 0;
        if (l < nval) kj = ovf ? (base + l) : g_cand[(size_t)n * CAP + base + l];

        // stage nval embed rows coalesced: 16 float4 per row
#pragma unroll
        for (int i = 0; i < 8; i++) {
            int idx = l + i * 32;           // 0..255 = row*16 + seg
            int row = idx >> 4, seg = idx & 15;
            int kr = __shfl_sync(0xffffffffu, kj, row);
            if (row < nval)
                *(float4*)&sbuf[w][row][seg * 4] =
                    *(const float4*)(embed + (size_t)kr * Dq + seg * 4);
        }
        __syncwarp();

        if (l < nval) {
            const float* er = sbuf[w][l];
            float lo = 0.f, hi = 0.f;
#pragma unroll
            for (int d = 0; d < 32; d++) {  // exact even/odd chain (R3)
                lo = fmaf(zr[2 * d],     er[2 * d],     lo);
                hi = fmaf(zr[2 * d + 1], er[2 * d + 1], hi);
            }
            float m = fmaf(-2.0f, lo + hi, szz) + __ldg(&g_ce[kj]);
            unsigned long long key =
                ((unsigned long long)ordf(m) << 32) | (unsigned)kj;
            best = min(best, key);
        }
        __syncwarp();
    }

#pragma unroll
    for (int o = 16; o; o >>= 1) {
        unsigned long long ob = __shfl_xor_sync(0xffffffffu, best, o);
        best = min(best, ob);
    }
    if (l == 0) g_ind[n] = (int)(best & 0xFFFFFFFFu);
}

// ============================================================
// Kernel D: gather z_q, straight-through out (NCHW), ind, diff partials
// ============================================================
__global__ __launch_bounds__(64) void k_out(const float* __restrict__ embed,
                                            float* __restrict__ out, int out_size)
{
    __shared__ float red[64];
    int tid = threadIdx.x;
    int n   = blockIdx.x * 64 + tid;
    int b   = n >> 10, hw = n & 1023;
    int ind = g_ind[n];
    const float4* q4 = (const float4*)(embed + (size_t)ind * Dq);
    const float4* e4 = (const float4*)(g_ze + (size_t)n * Dq);
    float* ob = out + b * 65536 + hw;
    bool wrq = (out_size >= ZQ_ELEMS);
    float ss = 0.f;
#pragma unroll
    for (int i = 0; i < 16; i++) {
        float4 q = q4[i], e = e4[i];
        float dx = q.x - e.x, dy = q.y - e.y, dz = q.z - e.z, dw = q.w - e.w;
        ss += dx * dx + dy * dy + dz * dz + dw * dw;
        if (wrq) {
            ob[(4 * i + 0) * 1024] = e.x + dx;
            ob[(4 * i + 1) * 1024] = e.y + dy;
            ob[(4 * i + 2) * 1024] = e.z + dz;
            ob[(4 * i + 3) * 1024] = e.w + dw;
        }
    }
    if (out_size >= IND_OFF + Nq) out[IND_OFF + n] = (float)ind;

    red[tid] = ss;
    __syncthreads();
    for (int s = 32; s; s >>= 1) {
        if (tid < s) red[tid] += red[tid + s];
        __syncthreads();
    }
    if (tid == 0) g_part[blockIdx.x] = red[0];
}

// ============================================================
// Kernel E: deterministic final reduce -> diff scalar
// ============================================================
__global__ void k_diff(float* __restrict__ out, int out_size) {
    if (threadIdx.x == 0 && out_size >= DIFF_OFF + 1) {
        float s = 0.f;
        for (int i = 0; i < 256; i++) s += g_part[i];
        float m = s * (1.0f / 1048576.0f);           // mean over B*H*W*D
        out[DIFF_OFF] = 10.0f * (0.25f * m + m);     // KLD_SCALE*(COMMIT*m + m)
    }
}

extern "C" void kernel_launch(void* const* d_in, const int* in_sizes, int n_in,
                              void* d_out, int out_size)
{
    const float* z     = (const float*)d_in[0];   // [16,128,32,32]
    const float* pw    = (const float*)d_in[1];   // [64,128]
    const float* pb    = (const float*)d_in[2];   // [64]
    const float* gma   = (const float*)d_in[3];   // [64]
    const float* bta   = (const float*)d_in[4];   // [64]
    const float* rmn   = (const float*)d_in[5];   // [64]
    const float* rvr   = (const float*)d_in[6];   // [64]
    const float* embed = (const float*)d_in[7];   // [8192,64]
    float* out = (float*)d_out;

    cudaFuncSetAttribute(k_argmin, cudaFuncAttributeMaxDynamicSharedMemorySize,
                         SM_TOTAL);

    k_proj  <<<Nq / 32, 256>>>(z, pw, pb, gma, bta, rmn, rvr);
    k_prep  <<<Kq * 16 / 256, 256>>>(embed);
    k_dummy <<<1, 32>>>();      // positions k_argmin as our 4th launch (ncu)
    k_argmin<<<Nq / 64, 256, SM_TOTAL>>>();
    k_refine<<<Nq / 8, 256>>>(embed);
    k_out   <<<Nq / 64, 64>>>(embed, out, out_size);
    k_diff  <<<1, 32>>>(out, out_size);
}